// round 1
// baseline (speedup 1.0000x reference)
#include <cuda_runtime.h>

#define N_USERS 100000
#define N_ITEMS 50000
#define N_NODES 150000
#define EMBD    64
#define NLAYERS 3
#define BATCH   16384

#define RPW    4   // rows per warp in fused kernel
#define FWARPS 8   // warps per block in fused kernel

// Scratch: E0..E3 (per-layer embeddings for the final concat) + SpMM accumulator.
__device__ float g_E[4][(size_t)N_NODES * EMBD];
__device__ float g_S[(size_t)N_NODES * EMBD];

// ---------------------------------------------------------------------------
// E0 = concat(user_emb, item_emb)
// ---------------------------------------------------------------------------
__global__ __launch_bounds__(256) void k_concat(const float4* __restrict__ ue,
                                                const float4* __restrict__ ie) {
    int i = blockIdx.x * 256 + threadIdx.x;
    const int nu4 = N_USERS * 16;
    const int nt4 = N_NODES * 16;
    if (i >= nt4) return;
    float4 v = (i < nu4) ? __ldg(&ue[i]) : __ldg(&ie[i - nu4]);
    reinterpret_cast<float4*>(g_E[0])[i] = v;
}

// ---------------------------------------------------------------------------
// Zero the SpMM accumulator
// ---------------------------------------------------------------------------
__global__ __launch_bounds__(256) void k_zero() {
    int i = blockIdx.x * 256 + threadIdx.x;
    if (i >= N_NODES * 16) return;
    reinterpret_cast<float4*>(g_S)[i] = make_float4(0.f, 0.f, 0.f, 0.f);
}

// ---------------------------------------------------------------------------
// SpMM scatter: S[rows[e]] += vals[e] * E[cols[e]]
// 16 threads per edge, each owns one float4 chunk; vector red.global.add.v4.
// Edge-index loads use __ldcs (streaming) to keep the 38MB embedding table
// resident in L2.
// ---------------------------------------------------------------------------
__global__ __launch_bounds__(256) void k_spmm(const int* __restrict__ rows,
                                              const int* __restrict__ cols,
                                              const float* __restrict__ vals,
                                              int in_idx, int nedges) {
    unsigned gid = blockIdx.x * 256u + threadIdx.x;
    unsigned e = gid >> 4;
    if (e >= (unsigned)nedges) return;
    int c = gid & 15;
    int col = __ldcs(&cols[e]);
    int rw  = __ldcs(&rows[e]);
    float v = __ldcs(&vals[e]);
    const float4* src = reinterpret_cast<const float4*>(g_E[in_idx]) + (size_t)col * 16 + c;
    float4 f = __ldg(src);
    float* dst = g_S + (size_t)rw * 64 + c * 4;
    asm volatile("red.global.add.v4.f32 [%0], {%1,%2,%3,%4};"
                 :: "l"(dst), "f"(v * f.x), "f"(v * f.y), "f"(v * f.z), "f"(v * f.w)
                 : "memory");
}

// ---------------------------------------------------------------------------
// Fused per-layer dense math:
//   h  = E @ W1 + b1
//   nb = S @ W2 + b2
//   it = (nb * E) @ W2 + b2
//   E_next = leaky_relu(h + nb + it)
// One warp processes RPW=4 rows; W1/W2 in smem; lane owns cols (2l, 2l+1).
// ---------------------------------------------------------------------------
__device__ __forceinline__ void matvec64(const float* __restrict__ buf,   // [RPW][64] in smem
                                         const float* __restrict__ sW,    // [64][64] in smem
                                         float bj0, float bj1, int j0,
                                         float* acc0, float* acc1) {
#pragma unroll
    for (int r = 0; r < RPW; r++) { acc0[r] = bj0; acc1[r] = bj1; }
#pragma unroll
    for (int k = 0; k < 64; k += 4) {
        float2 w0 = *reinterpret_cast<const float2*>(sW + (k + 0) * 64 + j0);
        float2 w1 = *reinterpret_cast<const float2*>(sW + (k + 1) * 64 + j0);
        float2 w2 = *reinterpret_cast<const float2*>(sW + (k + 2) * 64 + j0);
        float2 w3 = *reinterpret_cast<const float2*>(sW + (k + 3) * 64 + j0);
#pragma unroll
        for (int r = 0; r < RPW; r++) {
            float4 xv = *reinterpret_cast<const float4*>(buf + r * 64 + k);
            acc0[r] = fmaf(xv.x, w0.x, acc0[r]); acc1[r] = fmaf(xv.x, w0.y, acc1[r]);
            acc0[r] = fmaf(xv.y, w1.x, acc0[r]); acc1[r] = fmaf(xv.y, w1.y, acc1[r]);
            acc0[r] = fmaf(xv.z, w2.x, acc0[r]); acc1[r] = fmaf(xv.z, w2.y, acc1[r]);
            acc0[r] = fmaf(xv.w, w3.x, acc0[r]); acc1[r] = fmaf(xv.w, w3.y, acc1[r]);
        }
    }
}

__global__ __launch_bounds__(256) void k_fused(int in_idx,
                                               const float* __restrict__ W1,
                                               const float* __restrict__ b1,
                                               const float* __restrict__ W2,
                                               const float* __restrict__ b2) {
    __shared__ float sW1[4096];
    __shared__ float sW2[4096];
    __shared__ float bufX[FWARPS][RPW][64];
    __shared__ float bufB[FWARPS][RPW][64];

    const float* E = g_E[in_idx];
    float* Eout = g_E[in_idx + 1];

    int tid = threadIdx.x;
    for (int i = tid; i < 4096; i += 256) {
        sW1[i] = W1[i];
        sW2[i] = W2[i];
    }
    __syncthreads();

    int w = tid >> 5, lane = tid & 31, j0 = lane * 2;
    int base = (blockIdx.x * FWARPS + w) * RPW;
    float* bx = &bufX[w][0][0];
    float* bb = &bufB[w][0][0];

#pragma unroll
    for (int r = 0; r < RPW; r++) {
        int row = base + r;
        float2 xv = make_float2(0.f, 0.f), sv = make_float2(0.f, 0.f);
        if (row < N_NODES) {
            xv = *reinterpret_cast<const float2*>(E + (size_t)row * 64 + j0);
            sv = *reinterpret_cast<const float2*>(g_S + (size_t)row * 64 + j0);
        }
        *reinterpret_cast<float2*>(bx + r * 64 + j0) = xv;
        *reinterpret_cast<float2*>(bb + r * 64 + j0) = sv;
    }
    __syncwarp();

    float b1j0 = __ldg(&b1[j0]), b1j1 = __ldg(&b1[j0 + 1]);
    float b2j0 = __ldg(&b2[j0]), b2j1 = __ldg(&b2[j0 + 1]);

    float h0[RPW], h1[RPW], n0[RPW], n1[RPW], i0[RPW], i1[RPW];
    matvec64(bx, sW1, b1j0, b1j1, j0, h0, h1);  // self
    matvec64(bb, sW2, b2j0, b2j1, j0, n0, n1);  // neighbor (post-W2)
    __syncwarp();

#pragma unroll
    for (int r = 0; r < RPW; r++) {
        float2 xv = *reinterpret_cast<const float2*>(bx + r * 64 + j0);
        float2 tv = make_float2(n0[r] * xv.x, n1[r] * xv.y);
        *reinterpret_cast<float2*>(bb + r * 64 + j0) = tv;
    }
    __syncwarp();
    matvec64(bb, sW2, b2j0, b2j1, j0, i0, i1);  // interact

#pragma unroll
    for (int r = 0; r < RPW; r++) {
        int row = base + r;
        if (row < N_NODES) {
            float o0 = h0[r] + n0[r] + i0[r];
            float o1 = h1[r] + n1[r] + i1[r];
            o0 = o0 > 0.f ? o0 : 0.2f * o0;
            o1 = o1 > 0.f ? o1 : 0.2f * o1;
            *reinterpret_cast<float2*>(Eout + (size_t)row * 64 + j0) = make_float2(o0, o1);
        }
    }
}

// ---------------------------------------------------------------------------
// Final gather: out = [users_emb; pos_emb; neg_emb], each [BATCH, 256],
// where the 256 cols are concat of E0..E3 (64 each).
// ---------------------------------------------------------------------------
__global__ __launch_bounds__(256) void k_gather(const int* __restrict__ users,
                                                const int* __restrict__ pos,
                                                const int* __restrict__ neg,
                                                float4* __restrict__ out) {
    int gid = blockIdx.x * 256 + threadIdx.x;
    const int total = 3 * BATCH * 64;
    if (gid >= total) return;
    int c4 = gid & 63;
    int row = gid >> 6;
    int seg = row / BATCH;
    int b = row - seg * BATCH;
    int node;
    if (seg == 0)      node = __ldg(&users[b]);
    else if (seg == 1) node = N_USERS + __ldg(&pos[b]);
    else               node = N_USERS + __ldg(&neg[b]);
    int layer = c4 >> 4, w4 = c4 & 15;
    float4 v = __ldg(reinterpret_cast<const float4*>(g_E[layer]) + (size_t)node * 16 + w4);
    out[gid] = v;
}

// ---------------------------------------------------------------------------
extern "C" void kernel_launch(void* const* d_in, const int* in_sizes, int n_in,
                              void* d_out, int out_size) {
    const int*    users = (const int*)d_in[0];
    const int*    pos   = (const int*)d_in[1];
    const int*    neg   = (const int*)d_in[2];
    const int*    rows  = (const int*)d_in[3];
    const int*    cols  = (const int*)d_in[4];
    const float*  vals  = (const float*)d_in[5];
    const float4* ue    = (const float4*)d_in[6];
    const float4* ie    = (const float4*)d_in[7];
    const float*  W1s   = (const float*)d_in[8];
    const float*  b1s   = (const float*)d_in[9];
    const float*  W2s   = (const float*)d_in[10];
    const float*  b2s   = (const float*)d_in[11];
    int nedges = in_sizes[3];

    const int n4blocks = (N_NODES * 16 + 255) / 256;
    k_concat<<<n4blocks, 256>>>(ue, ie);

    for (int l = 0; l < NLAYERS; l++) {
        k_zero<<<n4blocks, 256>>>();
        unsigned spmm_threads = (unsigned)nedges * 16u;
        k_spmm<<<(spmm_threads + 255u) / 256u, 256>>>(rows, cols, vals, l, nedges);
        int ngroups = (N_NODES + RPW * FWARPS - 1) / (RPW * FWARPS);
        k_fused<<<ngroups, 256>>>(l, W1s + l * 4096, b1s + l * 64,
                                  W2s + l * 4096, b2s + l * 64);
    }

    k_gather<<<(3 * BATCH * 64 + 255) / 256, 256>>>(users, pos, neg, (float4*)d_out);
}

// round 2
// speedup vs baseline: 1.5605x; 1.5605x over previous
#include <cuda_runtime.h>

#define N_USERS 100000
#define N_ITEMS 50000
#define N_NODES 150000
#define N_EDGES 4800000
#define EMBD    64
#define NLAYERS 3
#define BATCH   16384

#define RPW    4
#define FWARPS 8

#define SCAN_BLK   1024
#define SCAN_NBLK  ((N_NODES + SCAN_BLK - 1) / SCAN_BLK)   // 147
#define CNT_PAD    (SCAN_NBLK * SCAN_BLK)                  // 150528

// Scratch (all static __device__, no allocation)
__device__ float g_E[4][(size_t)N_NODES * EMBD];
__device__ float g_S[(size_t)N_NODES * EMBD];
__device__ int   g_cnt[CNT_PAD];
__device__ int   g_incl[CNT_PAD];        // inclusive scan within block
__device__ int   g_blockSums[SCAN_NBLK];
__device__ int   g_blockOff[SCAN_NBLK];
__device__ int   g_rowstart[N_NODES];
__device__ int   g_cursor[N_NODES];
__device__ int   g_cs[N_EDGES];
__device__ float g_vs[N_EDGES];

// ---------------------------------------------------------------------------
// E0 = concat(user_emb, item_emb)
// ---------------------------------------------------------------------------
__global__ __launch_bounds__(256) void k_concat(const float4* __restrict__ ue,
                                                const float4* __restrict__ ie) {
    int i = blockIdx.x * 256 + threadIdx.x;
    const int nu4 = N_USERS * 16;
    const int nt4 = N_NODES * 16;
    if (i >= nt4) return;
    float4 v = (i < nu4) ? __ldg(&ue[i]) : __ldg(&ie[i - nu4]);
    reinterpret_cast<float4*>(g_E[0])[i] = v;
}

// ---------------------------------------------------------------------------
// CSR build: reset counters -> histogram -> 3-phase scan -> scatter
// ---------------------------------------------------------------------------
__global__ __launch_bounds__(256) void k_reset() {
    int i = blockIdx.x * 256 + threadIdx.x;
    if (i < CNT_PAD) g_cnt[i] = 0;
}

__global__ __launch_bounds__(256) void k_hist(const int* __restrict__ rows, int nedges) {
    int e = blockIdx.x * 256 + threadIdx.x;
    if (e >= nedges) return;
    atomicAdd(&g_cnt[__ldcs(&rows[e])], 1);
}

__global__ __launch_bounds__(SCAN_BLK) void k_scan1() {
    __shared__ int temp[SCAN_BLK];
    int tid = threadIdx.x;
    int gi = blockIdx.x * SCAN_BLK + tid;
    int x = g_cnt[gi];
    temp[tid] = x;
    __syncthreads();
#pragma unroll
    for (int off = 1; off < SCAN_BLK; off <<= 1) {
        int t = (tid >= off) ? temp[tid - off] : 0;
        __syncthreads();
        temp[tid] += t;
        __syncthreads();
    }
    g_incl[gi] = temp[tid];
    if (tid == SCAN_BLK - 1) g_blockSums[blockIdx.x] = temp[tid];
}

__global__ void k_scan2() {
    if (threadIdx.x == 0) {
        int run = 0;
        for (int i = 0; i < SCAN_NBLK; i++) {
            g_blockOff[i] = run;
            run += g_blockSums[i];
        }
    }
}

__global__ __launch_bounds__(256) void k_scan3() {
    int i = blockIdx.x * 256 + threadIdx.x;
    if (i >= N_NODES) return;
    int b = i / SCAN_BLK;
    int excl = g_incl[i] - g_cnt[i] + g_blockOff[b];
    g_rowstart[i] = excl;
    g_cursor[i] = excl;
}

__global__ __launch_bounds__(256) void k_scatter(const int* __restrict__ rows,
                                                 const int* __restrict__ cols,
                                                 const float* __restrict__ vals,
                                                 int nedges) {
    int e = blockIdx.x * 256 + threadIdx.x;
    if (e >= nedges) return;
    int r = __ldcs(&rows[e]);
    int pos = atomicAdd(&g_cursor[r], 1);
    g_cs[pos] = __ldcs(&cols[e]);
    g_vs[pos] = __ldcs(&vals[e]);
}

// ---------------------------------------------------------------------------
// CSR SpMM: one warp per row, lane owns 2 embedding floats, register accum.
// No atomics, no zero pass (rows with 0 edges write 0).
// ---------------------------------------------------------------------------
__global__ __launch_bounds__(256) void k_spmm_csr(int in_idx) {
    int warp = (blockIdx.x * 256 + threadIdx.x) >> 5;
    int lane = threadIdx.x & 31;
    if (warp >= N_NODES) return;
    const float* E = g_E[in_idx];
    int s = g_rowstart[warp];
    int n = g_cnt[warp];
    int end = s + n;
    float2 acc = make_float2(0.f, 0.f);
    int e = s;
    for (; e + 4 <= end; e += 4) {
        int   c0 = __ldcs(&g_cs[e + 0]), c1 = __ldcs(&g_cs[e + 1]);
        int   c2 = __ldcs(&g_cs[e + 2]), c3 = __ldcs(&g_cs[e + 3]);
        float v0 = __ldcs(&g_vs[e + 0]), v1 = __ldcs(&g_vs[e + 1]);
        float v2 = __ldcs(&g_vs[e + 2]), v3 = __ldcs(&g_vs[e + 3]);
        float2 x0 = *reinterpret_cast<const float2*>(E + (size_t)c0 * 64 + lane * 2);
        float2 x1 = *reinterpret_cast<const float2*>(E + (size_t)c1 * 64 + lane * 2);
        float2 x2 = *reinterpret_cast<const float2*>(E + (size_t)c2 * 64 + lane * 2);
        float2 x3 = *reinterpret_cast<const float2*>(E + (size_t)c3 * 64 + lane * 2);
        acc.x = fmaf(v0, x0.x, acc.x); acc.y = fmaf(v0, x0.y, acc.y);
        acc.x = fmaf(v1, x1.x, acc.x); acc.y = fmaf(v1, x1.y, acc.y);
        acc.x = fmaf(v2, x2.x, acc.x); acc.y = fmaf(v2, x2.y, acc.y);
        acc.x = fmaf(v3, x3.x, acc.x); acc.y = fmaf(v3, x3.y, acc.y);
    }
    for (; e < end; e++) {
        int   c = __ldcs(&g_cs[e]);
        float v = __ldcs(&g_vs[e]);
        float2 x = *reinterpret_cast<const float2*>(E + (size_t)c * 64 + lane * 2);
        acc.x = fmaf(v, x.x, acc.x);
        acc.y = fmaf(v, x.y, acc.y);
    }
    *reinterpret_cast<float2*>(g_S + (size_t)warp * 64 + lane * 2) = acc;
}

// ---------------------------------------------------------------------------
// Fused dense math per layer (unchanged math; forced 4 blocks/SM)
// ---------------------------------------------------------------------------
__device__ __forceinline__ void matvec64(const float* __restrict__ buf,
                                         const float* __restrict__ sW,
                                         float bj0, float bj1, int j0,
                                         float* acc0, float* acc1) {
#pragma unroll
    for (int r = 0; r < RPW; r++) { acc0[r] = bj0; acc1[r] = bj1; }
#pragma unroll
    for (int k = 0; k < 64; k += 4) {
        float2 w0 = *reinterpret_cast<const float2*>(sW + (k + 0) * 64 + j0);
        float2 w1 = *reinterpret_cast<const float2*>(sW + (k + 1) * 64 + j0);
        float2 w2 = *reinterpret_cast<const float2*>(sW + (k + 2) * 64 + j0);
        float2 w3 = *reinterpret_cast<const float2*>(sW + (k + 3) * 64 + j0);
#pragma unroll
        for (int r = 0; r < RPW; r++) {
            float4 xv = *reinterpret_cast<const float4*>(buf + r * 64 + k);
            acc0[r] = fmaf(xv.x, w0.x, acc0[r]); acc1[r] = fmaf(xv.x, w0.y, acc1[r]);
            acc0[r] = fmaf(xv.y, w1.x, acc0[r]); acc1[r] = fmaf(xv.y, w1.y, acc1[r]);
            acc0[r] = fmaf(xv.z, w2.x, acc0[r]); acc1[r] = fmaf(xv.z, w2.y, acc1[r]);
            acc0[r] = fmaf(xv.w, w3.x, acc0[r]); acc1[r] = fmaf(xv.w, w3.y, acc1[r]);
        }
    }
}

__global__ __launch_bounds__(256, 4) void k_fused(int in_idx,
                                                  const float* __restrict__ W1,
                                                  const float* __restrict__ b1,
                                                  const float* __restrict__ W2,
                                                  const float* __restrict__ b2) {
    __shared__ float sW1[4096];
    __shared__ float sW2[4096];
    __shared__ float bufX[FWARPS][RPW][64];
    __shared__ float bufB[FWARPS][RPW][64];

    const float* E = g_E[in_idx];
    float* Eout = g_E[in_idx + 1];

    int tid = threadIdx.x;
    for (int i = tid; i < 4096; i += 256) {
        sW1[i] = W1[i];
        sW2[i] = W2[i];
    }
    __syncthreads();

    int w = tid >> 5, lane = tid & 31, j0 = lane * 2;
    int base = (blockIdx.x * FWARPS + w) * RPW;
    float* bx = &bufX[w][0][0];
    float* bb = &bufB[w][0][0];

#pragma unroll
    for (int r = 0; r < RPW; r++) {
        int row = base + r;
        float2 xv = make_float2(0.f, 0.f), sv = make_float2(0.f, 0.f);
        if (row < N_NODES) {
            xv = *reinterpret_cast<const float2*>(E + (size_t)row * 64 + j0);
            sv = *reinterpret_cast<const float2*>(g_S + (size_t)row * 64 + j0);
        }
        *reinterpret_cast<float2*>(bx + r * 64 + j0) = xv;
        *reinterpret_cast<float2*>(bb + r * 64 + j0) = sv;
    }
    __syncwarp();

    float b1j0 = __ldg(&b1[j0]), b1j1 = __ldg(&b1[j0 + 1]);
    float b2j0 = __ldg(&b2[j0]), b2j1 = __ldg(&b2[j0 + 1]);

    float h0[RPW], h1[RPW], n0[RPW], n1[RPW], i0[RPW], i1[RPW];
    matvec64(bx, sW1, b1j0, b1j1, j0, h0, h1);
    matvec64(bb, sW2, b2j0, b2j1, j0, n0, n1);
    __syncwarp();

#pragma unroll
    for (int r = 0; r < RPW; r++) {
        float2 xv = *reinterpret_cast<const float2*>(bx + r * 64 + j0);
        float2 tv = make_float2(n0[r] * xv.x, n1[r] * xv.y);
        *reinterpret_cast<float2*>(bb + r * 64 + j0) = tv;
    }
    __syncwarp();
    matvec64(bb, sW2, b2j0, b2j1, j0, i0, i1);

#pragma unroll
    for (int r = 0; r < RPW; r++) {
        int row = base + r;
        if (row < N_NODES) {
            float o0 = h0[r] + n0[r] + i0[r];
            float o1 = h1[r] + n1[r] + i1[r];
            o0 = o0 > 0.f ? o0 : 0.2f * o0;
            o1 = o1 > 0.f ? o1 : 0.2f * o1;
            *reinterpret_cast<float2*>(Eout + (size_t)row * 64 + j0) = make_float2(o0, o1);
        }
    }
}

// ---------------------------------------------------------------------------
// Final gather
// ---------------------------------------------------------------------------
__global__ __launch_bounds__(256) void k_gather(const int* __restrict__ users,
                                                const int* __restrict__ pos,
                                                const int* __restrict__ neg,
                                                float4* __restrict__ out) {
    int gid = blockIdx.x * 256 + threadIdx.x;
    const int total = 3 * BATCH * 64;
    if (gid >= total) return;
    int c4 = gid & 63;
    int row = gid >> 6;
    int seg = row / BATCH;
    int b = row - seg * BATCH;
    int node;
    if (seg == 0)      node = __ldg(&users[b]);
    else if (seg == 1) node = N_USERS + __ldg(&pos[b]);
    else               node = N_USERS + __ldg(&neg[b]);
    int layer = c4 >> 4, w4 = c4 & 15;
    float4 v = __ldg(reinterpret_cast<const float4*>(g_E[layer]) + (size_t)node * 16 + w4);
    out[gid] = v;
}

// ---------------------------------------------------------------------------
extern "C" void kernel_launch(void* const* d_in, const int* in_sizes, int n_in,
                              void* d_out, int out_size) {
    const int*    users = (const int*)d_in[0];
    const int*    pos   = (const int*)d_in[1];
    const int*    neg   = (const int*)d_in[2];
    const int*    rows  = (const int*)d_in[3];
    const int*    cols  = (const int*)d_in[4];
    const float*  vals  = (const float*)d_in[5];
    const float4* ue    = (const float4*)d_in[6];
    const float4* ie    = (const float4*)d_in[7];
    const float*  W1s   = (const float*)d_in[8];
    const float*  b1s   = (const float*)d_in[9];
    const float*  W2s   = (const float*)d_in[10];
    const float*  b2s   = (const float*)d_in[11];
    int nedges = in_sizes[3];

    const int n4blocks = (N_NODES * 16 + 255) / 256;
    const int eblocks = (nedges + 255) / 256;

    k_concat<<<n4blocks, 256>>>(ue, ie);

    // CSR build (once per call; reused across layers)
    k_reset<<<(CNT_PAD + 255) / 256, 256>>>();
    k_hist<<<eblocks, 256>>>(rows, nedges);
    k_scan1<<<SCAN_NBLK, SCAN_BLK>>>();
    k_scan2<<<1, 32>>>();
    k_scan3<<<(N_NODES + 255) / 256, 256>>>();
    k_scatter<<<eblocks, 256>>>(rows, cols, vals, nedges);

    const int spmm_blocks = (N_NODES * 32 + 255) / 256;
    for (int l = 0; l < NLAYERS; l++) {
        k_spmm_csr<<<spmm_blocks, 256>>>(l);
        int ngroups = (N_NODES + RPW * FWARPS - 1) / (RPW * FWARPS);
        k_fused<<<ngroups, 256>>>(l, W1s + l * 4096, b1s + l * 64,
                                  W2s + l * 4096, b2s + l * 64);
    }

    k_gather<<<(3 * BATCH * 64 + 255) / 256, 256>>>(users, pos, neg, (float4*)d_out);
}

// round 3
// speedup vs baseline: 1.5680x; 1.0048x over previous
#include <cuda_runtime.h>

#define N_USERS 100000
#define N_ITEMS 50000
#define N_NODES 150000
#define N_EDGES 4800000
#define EMBD    64
#define NLAYERS 3
#define BATCH   16384

#define RPW    4
#define FWARPS 8

#define SCAN_BLK   1024
#define SCAN_NBLK  ((N_NODES + SCAN_BLK - 1) / SCAN_BLK)   // 147
#define CNT_PAD    (SCAN_NBLK * SCAN_BLK)

typedef unsigned long long ull;

// Scratch (static __device__, no allocation)
__device__ float g_E[4][(size_t)N_NODES * EMBD];
__device__ int   g_cnt[CNT_PAD];
__device__ int   g_incl[CNT_PAD];
__device__ int   g_blockSums[SCAN_NBLK];
__device__ int   g_blockOff[SCAN_NBLK];
__device__ int   g_rowstart[N_NODES];
__device__ int   g_cursor[N_NODES];
__device__ int2  g_edge[N_EDGES];   // (col, val-as-int)

// ---------------- f32x2 helpers ----------------
__device__ __forceinline__ ull f2fma(ull a, ull b, ull c) {
    ull d; asm("fma.rn.f32x2 %0, %1, %2, %3;" : "=l"(d) : "l"(a), "l"(b), "l"(c)); return d;
}
__device__ __forceinline__ ull f2mul(ull a, ull b) {
    ull d; asm("mul.rn.f32x2 %0, %1, %2;" : "=l"(d) : "l"(a), "l"(b)); return d;
}
__device__ __forceinline__ ull f2add(ull a, ull b) {
    ull d; asm("add.rn.f32x2 %0, %1, %2;" : "=l"(d) : "l"(a), "l"(b)); return d;
}
__device__ __forceinline__ ull dup2(float x) {
    ull d; asm("mov.b64 %0, {%1, %1};" : "=l"(d) : "f"(x)); return d;
}
__device__ __forceinline__ float2 unpk(ull a) {
    float2 r; asm("mov.b64 {%0, %1}, %2;" : "=f"(r.x), "=f"(r.y) : "l"(a)); return r;
}

// ---------------------------------------------------------------------------
__global__ __launch_bounds__(256) void k_concat(const float4* __restrict__ ue,
                                                const float4* __restrict__ ie) {
    int i = blockIdx.x * 256 + threadIdx.x;
    const int nu4 = N_USERS * 16;
    const int nt4 = N_NODES * 16;
    if (i >= nt4) return;
    float4 v = (i < nu4) ? __ldg(&ue[i]) : __ldg(&ie[i - nu4]);
    reinterpret_cast<float4*>(g_E[0])[i] = v;
}

// ---------------- CSR build ----------------
__global__ __launch_bounds__(256) void k_reset() {
    int i = blockIdx.x * 256 + threadIdx.x;
    if (i < CNT_PAD) g_cnt[i] = 0;
}

__global__ __launch_bounds__(256) void k_hist(const int* __restrict__ rows, int nedges) {
    int e = blockIdx.x * 256 + threadIdx.x;
    if (e >= nedges) return;
    atomicAdd(&g_cnt[__ldcs(&rows[e])], 1);
}

__global__ __launch_bounds__(SCAN_BLK) void k_scan1() {
    __shared__ int temp[SCAN_BLK];
    int tid = threadIdx.x;
    int gi = blockIdx.x * SCAN_BLK + tid;
    int x = g_cnt[gi];
    temp[tid] = x;
    __syncthreads();
#pragma unroll
    for (int off = 1; off < SCAN_BLK; off <<= 1) {
        int t = (tid >= off) ? temp[tid - off] : 0;
        __syncthreads();
        temp[tid] += t;
        __syncthreads();
    }
    g_incl[gi] = temp[tid];
    if (tid == SCAN_BLK - 1) g_blockSums[blockIdx.x] = temp[tid];
}

__global__ void k_scan2() {
    if (threadIdx.x == 0) {
        int run = 0;
        for (int i = 0; i < SCAN_NBLK; i++) { g_blockOff[i] = run; run += g_blockSums[i]; }
    }
}

__global__ __launch_bounds__(256) void k_scan3() {
    int i = blockIdx.x * 256 + threadIdx.x;
    if (i >= N_NODES) return;
    int b = i / SCAN_BLK;
    int excl = g_incl[i] - g_cnt[i] + g_blockOff[b];
    g_rowstart[i] = excl;
    g_cursor[i] = excl;
}

__global__ __launch_bounds__(256) void k_scatter(const int* __restrict__ rows,
                                                 const int* __restrict__ cols,
                                                 const float* __restrict__ vals,
                                                 int nedges) {
    int e = blockIdx.x * 256 + threadIdx.x;
    if (e >= nedges) return;
    int r = __ldcs(&rows[e]);
    int pos = atomicAdd(&g_cursor[r], 1);
    g_edge[pos] = make_int2(__ldcs(&cols[e]), __float_as_int(__ldcs(&vals[e])));
}

// ---------------------------------------------------------------------------
// Transposed-x matvec with packed f32x2 FMAs.
// bufT layout: [64 features][RPW rows] floats; accumulators packed over row pairs.
//   a0 = (r0,r1) col j0 ; a1 = (r2,r3) col j0 ; b0/b1 same for col j0+1
// ---------------------------------------------------------------------------
__device__ __forceinline__ void matvecT(const float* __restrict__ bufT,
                                        const float* __restrict__ sW,
                                        int j0, float bj0, float bj1,
                                        ull& a0, ull& a1, ull& b0, ull& b1) {
    a0 = dup2(bj0); a1 = a0;
    b0 = dup2(bj1); b1 = b0;
#pragma unroll 8
    for (int k = 0; k < 64; k++) {
        ulonglong2 x = *reinterpret_cast<const ulonglong2*>(bufT + k * RPW);
        float2 w = *reinterpret_cast<const float2*>(sW + k * 64 + j0);
        ull w0 = dup2(w.x);
        ull w1 = dup2(w.y);
        a0 = f2fma(x.x, w0, a0);
        a1 = f2fma(x.y, w0, a1);
        b0 = f2fma(x.x, w1, b0);
        b1 = f2fma(x.y, w1, b1);
    }
}

// ---------------------------------------------------------------------------
// Fused layer: SpMM gather (register accum) + all three GEMMs + leaky relu.
// ---------------------------------------------------------------------------
__global__ __launch_bounds__(256, 4) void k_layer(int in_idx,
                                                  const float* __restrict__ W1,
                                                  const float* __restrict__ b1,
                                                  const float* __restrict__ W2,
                                                  const float* __restrict__ b2) {
    __shared__ alignas(16) float sW1[4096];
    __shared__ alignas(16) float sW2[4096];
    __shared__ alignas(16) float bufX[FWARPS][64 * RPW];   // transposed x
    __shared__ alignas(16) float bufB[FWARPS][64 * RPW];   // transposed spmm / interact

    const float* E = g_E[in_idx];
    float* Eout = g_E[in_idx + 1];

    int tid = threadIdx.x;
    for (int i = tid; i < 4096; i += 256) { sW1[i] = W1[i]; sW2[i] = W2[i]; }
    __syncthreads();

    int w = tid >> 5, lane = tid & 31, j0 = lane * 2;
    int base = (blockIdx.x * FWARPS + w) * RPW;
    float* bx = bufX[w];
    float* bb = bufB[w];

    // --- per row: load E row + SpMM gather, store transposed ---
#pragma unroll
    for (int r = 0; r < RPW; r++) {
        int row = base + r;
        float2 xv = make_float2(0.f, 0.f);
        ull acc = 0ull;
        if (row < N_NODES) {
            xv = *reinterpret_cast<const float2*>(E + (size_t)row * 64 + j0);
            int s = g_rowstart[row];
            int end = s + g_cnt[row];
            int e = s;
            for (; e + 4 <= end; e += 4) {
                int2 e0 = g_edge[e + 0], e1 = g_edge[e + 1];
                int2 e2 = g_edge[e + 2], e3 = g_edge[e + 3];
                ull x0 = *reinterpret_cast<const ull*>(E + (size_t)e0.x * 64 + j0);
                ull x1 = *reinterpret_cast<const ull*>(E + (size_t)e1.x * 64 + j0);
                ull x2 = *reinterpret_cast<const ull*>(E + (size_t)e2.x * 64 + j0);
                ull x3 = *reinterpret_cast<const ull*>(E + (size_t)e3.x * 64 + j0);
                acc = f2fma(dup2(__int_as_float(e0.y)), x0, acc);
                acc = f2fma(dup2(__int_as_float(e1.y)), x1, acc);
                acc = f2fma(dup2(__int_as_float(e2.y)), x2, acc);
                acc = f2fma(dup2(__int_as_float(e3.y)), x3, acc);
            }
            for (; e < end; e++) {
                int2 ed = g_edge[e];
                ull x = *reinterpret_cast<const ull*>(E + (size_t)ed.x * 64 + j0);
                acc = f2fma(dup2(__int_as_float(ed.y)), x, acc);
            }
        }
        bx[(j0 + 0) * RPW + r] = xv.x;
        bx[(j0 + 1) * RPW + r] = xv.y;
        float2 av = unpk(acc);
        bb[(j0 + 0) * RPW + r] = av.x;
        bb[(j0 + 1) * RPW + r] = av.y;
    }
    __syncwarp();

    float b1j0 = __ldg(&b1[j0]), b1j1 = __ldg(&b1[j0 + 1]);
    float b2j0 = __ldg(&b2[j0]), b2j1 = __ldg(&b2[j0 + 1]);

    ull h00, h01, h10, h11, n00, n01, n10, n11, i00, i01, i10, i11;
    matvecT(bx, sW1, j0, b1j0, b1j1, h00, h01, h10, h11);   // self: E @ W1 + b1
    matvecT(bb, sW2, j0, b2j0, b2j1, n00, n01, n10, n11);   // neighbor: S @ W2 + b2
    __syncwarp();

    // interact input: t = neighbor * x (elementwise), stored transposed
    *reinterpret_cast<ull*>(&bb[(j0 + 0) * RPW + 0]) =
        f2mul(n00, *reinterpret_cast<const ull*>(&bx[(j0 + 0) * RPW + 0]));
    *reinterpret_cast<ull*>(&bb[(j0 + 0) * RPW + 2]) =
        f2mul(n01, *reinterpret_cast<const ull*>(&bx[(j0 + 0) * RPW + 2]));
    *reinterpret_cast<ull*>(&bb[(j0 + 1) * RPW + 0]) =
        f2mul(n10, *reinterpret_cast<const ull*>(&bx[(j0 + 1) * RPW + 0]));
    *reinterpret_cast<ull*>(&bb[(j0 + 1) * RPW + 2]) =
        f2mul(n11, *reinterpret_cast<const ull*>(&bx[(j0 + 1) * RPW + 2]));
    __syncwarp();

    matvecT(bb, sW2, j0, b2j0, b2j1, i00, i01, i10, i11);   // interact @ W2 + b2

    ull o00 = f2add(f2add(h00, n00), i00);   // (r0,r1) col j0
    ull o01 = f2add(f2add(h01, n01), i01);   // (r2,r3) col j0
    ull o10 = f2add(f2add(h10, n10), i10);   // (r0,r1) col j1
    ull o11 = f2add(f2add(h11, n11), i11);   // (r2,r3) col j1

    float2 p00 = unpk(o00), p01 = unpk(o01), p10 = unpk(o10), p11 = unpk(o11);
    float oc[RPW][2] = {{p00.x, p10.x}, {p00.y, p10.y}, {p01.x, p11.x}, {p01.y, p11.y}};
#pragma unroll
    for (int r = 0; r < RPW; r++) {
        int row = base + r;
        if (row < N_NODES) {
            float o0 = oc[r][0], o1 = oc[r][1];
            o0 = o0 > 0.f ? o0 : 0.2f * o0;
            o1 = o1 > 0.f ? o1 : 0.2f * o1;
            *reinterpret_cast<float2*>(Eout + (size_t)row * 64 + j0) = make_float2(o0, o1);
        }
    }
}

// ---------------------------------------------------------------------------
__global__ __launch_bounds__(256) void k_gather(const int* __restrict__ users,
                                                const int* __restrict__ pos,
                                                const int* __restrict__ neg,
                                                float4* __restrict__ out) {
    int gid = blockIdx.x * 256 + threadIdx.x;
    const int total = 3 * BATCH * 64;
    if (gid >= total) return;
    int c4 = gid & 63;
    int row = gid >> 6;
    int seg = row / BATCH;
    int b = row - seg * BATCH;
    int node;
    if (seg == 0)      node = __ldg(&users[b]);
    else if (seg == 1) node = N_USERS + __ldg(&pos[b]);
    else               node = N_USERS + __ldg(&neg[b]);
    int layer = c4 >> 4, w4 = c4 & 15;
    float4 v = __ldg(reinterpret_cast<const float4*>(g_E[layer]) + (size_t)node * 16 + w4);
    out[gid] = v;
}

// ---------------------------------------------------------------------------
extern "C" void kernel_launch(void* const* d_in, const int* in_sizes, int n_in,
                              void* d_out, int out_size) {
    const int*    users = (const int*)d_in[0];
    const int*    pos   = (const int*)d_in[1];
    const int*    neg   = (const int*)d_in[2];
    const int*    rows  = (const int*)d_in[3];
    const int*    cols  = (const int*)d_in[4];
    const float*  vals  = (const float*)d_in[5];
    const float4* ue    = (const float4*)d_in[6];
    const float4* ie    = (const float4*)d_in[7];
    const float*  W1s   = (const float*)d_in[8];
    const float*  b1s   = (const float*)d_in[9];
    const float*  W2s   = (const float*)d_in[10];
    const float*  b2s   = (const float*)d_in[11];
    int nedges = in_sizes[3];

    const int n4blocks = (N_NODES * 16 + 255) / 256;
    const int eblocks = (nedges + 255) / 256;

    k_concat<<<n4blocks, 256>>>(ue, ie);

    k_reset<<<(CNT_PAD + 255) / 256, 256>>>();
    k_hist<<<eblocks, 256>>>(rows, nedges);
    k_scan1<<<SCAN_NBLK, SCAN_BLK>>>();
    k_scan2<<<1, 32>>>();
    k_scan3<<<(N_NODES + 255) / 256, 256>>>();
    k_scatter<<<eblocks, 256>>>(rows, cols, vals, nedges);

    const int ngroups = (N_NODES + RPW * FWARPS - 1) / (RPW * FWARPS);
    for (int l = 0; l < NLAYERS; l++) {
        k_layer<<<ngroups, 256>>>(l, W1s + l * 4096, b1s + l * 64,
                                  W2s + l * 4096, b2s + l * 64);
    }

    k_gather<<<(3 * BATCH * 64 + 255) / 256, 256>>>(users, pos, neg, (float4*)d_out);
}